// round 1
// baseline (speedup 1.0000x reference)
#include <cuda_runtime.h>
#include <cstdint>
#include <cstddef>

#define CHN 128
#define IMGH 48
#define IMGW 48
#define NPIX 2304              // 48*48
#define NHEAD 8
#define HDIM 16

// ---------------- scratch (device globals; no allocation) ----------------
__device__ float g_conv[6][CHN * NPIX];   // qr,qi,kr,ki,vr,vi in (c,y,x)
__device__ float g_head[6][CHN * NPIX];   // qm,qp,km,kp,vm,vp in [h][n][16]
__device__ float g_ar[CHN * NPIX];        // attention out real (c,y,x)
__device__ float g_ai[CHN * NPIX];        // attention out imag (c,y,x)

// ---------------- complex 3x3 conv, padding 1 ----------------
// block (48, 8): tx = output x, ty = local co ; grid (16 co-blocks, 48 rows)
#define CO_T 8
#define CI_T 16

__global__ __launch_bounds__(384) void cconv_kernel(
    const float* __restrict__ xr_in, const float* __restrict__ xi_in,
    const float* __restrict__ wr, const float* __restrict__ wi,
    const float* __restrict__ br, const float* __restrict__ bi,
    float* __restrict__ yr_ext, float* __restrict__ yi_ext,
    int in_sel, int out_sel)
{
    __shared__ float xs_r[CI_T][3][IMGW + 2];
    __shared__ float xs_i[CI_T][3][IMGW + 2];
    __shared__ float ws_r[CO_T][CI_T][9];
    __shared__ float ws_i[CO_T][CI_T][9];

    const float* xr = in_sel ? g_ar : xr_in;
    const float* xi = in_sel ? g_ai : xi_in;
    float* yr = (out_sel < 3) ? g_conv[out_sel * 2] : yr_ext;
    float* yi = (out_sel < 3) ? g_conv[out_sel * 2 + 1] : yi_ext;

    const int tx = threadIdx.x;                // 0..47
    const int ty = threadIdx.y;                // 0..7
    const int y  = blockIdx.y;
    const int co = blockIdx.x * CO_T + ty;
    const int tid = ty * 48 + tx;              // 0..383

    float acc_r = 0.f, acc_i = 0.f;

    for (int ci0 = 0; ci0 < CHN; ci0 += CI_T) {
        __syncthreads();
        // load x tile: CI_T x 3 rows x 50 cols (zero-padded halo)
        for (int idx = tid; idx < CI_T * 3 * (IMGW + 2); idx += 384) {
            int ci  = idx / (3 * (IMGW + 2));
            int rem = idx % (3 * (IMGW + 2));
            int ry  = rem / (IMGW + 2);
            int rx  = rem % (IMGW + 2);
            int gy  = y + ry - 1;
            int gx  = rx - 1;
            float vr = 0.f, vi = 0.f;
            if (gy >= 0 && gy < IMGH && gx >= 0 && gx < IMGW) {
                int g = (ci0 + ci) * NPIX + gy * IMGW + gx;
                vr = xr[g]; vi = xi[g];
            }
            xs_r[ci][ry][rx] = vr;
            xs_i[ci][ry][rx] = vi;
        }
        // load weights for this co block / ci chunk
        for (int idx = tid; idx < CO_T * CI_T * 9; idx += 384) {
            int col = idx / (CI_T * 9);
            int rem = idx % (CI_T * 9);
            int ci  = rem / 9;
            int k   = rem % 9;
            int gw  = (blockIdx.x * CO_T + col) * CHN * 9 + (ci0 + ci) * 9 + k;
            ws_r[col][ci][k] = wr[gw];
            ws_i[col][ci][k] = wi[gw];
        }
        __syncthreads();

        #pragma unroll 2
        for (int ci = 0; ci < CI_T; ci++) {
            #pragma unroll
            for (int ky = 0; ky < 3; ky++) {
                #pragma unroll
                for (int kx = 0; kx < 3; kx++) {
                    float xrv = xs_r[ci][ky][tx + kx];
                    float xiv = xs_i[ci][ky][tx + kx];
                    float wrv = ws_r[ty][ci][ky * 3 + kx];
                    float wiv = ws_i[ty][ci][ky * 3 + kx];
                    acc_r = fmaf(xrv, wrv, acc_r);
                    acc_r = fmaf(-xiv, wiv, acc_r);
                    acc_i = fmaf(xrv, wiv, acc_i);
                    acc_i = fmaf(xiv, wrv, acc_i);
                }
            }
        }
    }
    acc_r += br[co];
    acc_i += bi[co];
    yr[co * NPIX + y * IMGW + tx] = acc_r;
    yi[co * NPIX + y * IMGW + tx] = acc_i;
}

// ---------------- rotary + magnitude/phase into head layout ----------------
// one thread per (tensor, head, n, channel-pair); tensors: 0=q,1=k,2=v
__global__ __launch_bounds__(256) void transform_kernel()
{
    int gid = blockIdx.x * blockDim.x + threadIdx.x;
    const int TOT = 3 * NHEAD * NPIX * (HDIM / 2);
    if (gid >= TOT) return;
    int pair = gid & 7;
    int t2 = gid >> 3;
    int n  = t2 % NPIX;
    int t3 = t2 / NPIX;
    int h  = t3 & 7;
    int tensor = t3 >> 3;

    int c0 = h * HDIM + pair * 2;
    const float* tr = g_conv[tensor * 2];
    const float* ti = g_conv[tensor * 2 + 1];
    float r0 = tr[c0 * NPIX + n], r1 = tr[(c0 + 1) * NPIX + n];
    float i0 = ti[c0 * NPIX + n], i1 = ti[(c0 + 1) * NPIX + n];

    if (tensor < 2) {
        double invf = pow(10000.0, -(double)(2 * pair) / 16.0);
        float f = (float)((double)n * invf);
        float sn, cs;
        sincosf(f, &sn, &cs);
        float nr0 = r0 * cs - r1 * sn, nr1 = r1 * cs + r0 * sn;
        float ni0 = i0 * cs - i1 * sn, ni1 = i1 * cs + i0 * sn;
        r0 = nr0; r1 = nr1; i0 = ni0; i1 = ni1;
    }
    float m0 = sqrtf(r0 * r0 + i0 * i0), p0 = atan2f(i0, r0);
    float m1 = sqrtf(r1 * r1 + i1 * i1), p1 = atan2f(i1, r1);

    float* om = g_head[tensor * 2];
    float* op = g_head[tensor * 2 + 1];
    int base = (h * NPIX + n) * HDIM + pair * 2;
    om[base] = m0; om[base + 1] = m1;
    op[base] = p0; op[base + 1] = p1;
}

// ---------------- attention ----------------
// block: 256 threads = 128 q-rows x 2 key-splits; grid (18 q-tiles, 8 heads)
#define NQ 128
#define TK 32
#define TKP (TK + 2)

__global__ __launch_bounds__(256) void attn_kernel(
    float* __restrict__ qkm_o, float* __restrict__ qkp_o)
{
    __shared__ float km_s[TK][16], kp_s[TK][16], vm_s[TK][16], vp_s[TK][16];
    __shared__ float sm_s[NQ][TKP], sp_s[NQ][TKP];
    __shared__ float red_m[256], red_l[256];

    const int h  = blockIdx.y;
    const int q0 = blockIdx.x * NQ;
    const int t  = threadIdx.x;
    const int s  = t >> 7;          // key split 0/1
    const int r  = t & 127;         // q row in tile
    const int qi = q0 + r;
    const float scale = 0.14433756729740643f;   // 1/sqrt(48)

    // load q row (mag + phase) into registers
    float qmr[16], qpr[16];
    {
        size_t base16 = ((size_t)(h * NPIX + qi)) * 16;
        #pragma unroll
        for (int d4 = 0; d4 < 4; d4++) {
            float4 a = ((const float4*)(g_head[0] + base16))[d4];
            float4 b = ((const float4*)(g_head[1] + base16))[d4];
            qmr[4*d4+0]=a.x; qmr[4*d4+1]=a.y; qmr[4*d4+2]=a.z; qmr[4*d4+3]=a.w;
            qpr[4*d4+0]=b.x; qpr[4*d4+1]=b.y; qpr[4*d4+2]=b.z; qpr[4*d4+3]=b.w;
        }
    }

    float mmax = -1e30f, lsum = 0.f;
    float am[16], ap[16];
    #pragma unroll
    for (int d = 0; d < 16; d++) { am[d] = 0.f; ap[d] = 0.f; }

    for (int kt = 0; kt < NPIX; kt += TK) {
        __syncthreads();
        // cooperative load of 32 keys (km,kp,vm,vp) : 512 float4 chunks
        #pragma unroll
        for (int rep = 0; rep < 2; rep++) {
            int idx = t + rep * 256;
            int tn = idx >> 7;           // 0..3
            int ch = idx & 127;
            size_t gbase = ((size_t)(h * NPIX + kt)) * 16;
            float4 v = ((const float4*)(g_head[2 + tn] + gbase))[ch];
            float4* dst = (tn == 0) ? (float4*)km_s :
                          (tn == 1) ? (float4*)kp_s :
                          (tn == 2) ? (float4*)vm_s : (float4*)vp_s;
            dst[ch] = v;
        }
        __syncthreads();

        // each thread: 16 keys of this tile (contiguous per split)
        #pragma unroll 2
        for (int jj = 0; jj < TK / 2; jj++) {
            int j = s * (TK / 2) + jj;
            float dm0 = 0.f, dm1 = 0.f, dp0 = 0.f, dp1 = 0.f;
            #pragma unroll
            for (int d = 0; d < 16; d += 2) {
                dm0 = fmaf(qmr[d],     km_s[j][d],     dm0);
                dm1 = fmaf(qmr[d + 1], km_s[j][d + 1], dm1);
                dp0 = fmaf(qpr[d],     kp_s[j][d],     dp0);
                dp1 = fmaf(qpr[d + 1], kp_s[j][d + 1], dp1);
            }
            float smv = (dm0 + dm1) * scale;
            float spv = (dp0 + dp1) * scale;
            sm_s[r][j] = smv;
            sp_s[r][j] = spv;

            float a = fabsf(smv);
            float p;
            if (a > mmax) {
                float corr = __expf(mmax - a);
                mmax = a;
                lsum *= corr;
                #pragma unroll
                for (int d = 0; d < 16; d++) { am[d] *= corr; ap[d] *= corr; }
                p = 1.f;
            } else {
                p = __expf(a - mmax);
            }
            lsum += p;
            #pragma unroll
            for (int d = 0; d < 16; d++) {
                am[d] = fmaf(p, vm_s[j][d], am[d]);
                ap[d] = fmaf(p, vp_s[j][d], ap[d]);
            }
        }
        __syncthreads();

        // coalesced writeout of score tile (both matrices), float2
        for (int i = t; i < NQ * (TK / 2); i += 256) {
            int row = i >> 4;               // TK/2 == 16
            int j2  = (i & 15) << 1;
            size_t g = ((size_t)h * NPIX + q0 + row) * NPIX + kt + j2;
            *(float2*)(qkm_o + g) = *(const float2*)&sm_s[row][j2];
            *(float2*)(qkp_o + g) = *(const float2*)&sp_s[row][j2];
        }
    }

    // combine the two key-splits per q row
    __syncthreads();
    red_m[t] = mmax;
    red_l[t] = lsum;
    if (s == 1) {
        #pragma unroll
        for (int d = 0; d < 16; d++) {
            sm_s[r][d]      = am[d];
            sp_s[r][d]      = ap[d];
        }
    }
    __syncthreads();
    if (s == 0) {
        float m1 = red_m[r + 128], l1 = red_l[r + 128];
        float M  = fmaxf(mmax, m1);
        float c0 = __expf(mmax - M), c1 = __expf(m1 - M);
        float L  = lsum * c0 + l1 * c1;
        float invL = 1.f / L;
        #pragma unroll
        for (int d = 0; d < 16; d++) {
            float omag = (am[d] * c0 + sm_s[r][d] * c1) * invL;
            float oph  = (ap[d] * c0 + sp_s[r][d] * c1) * invL;
            float sn, cs;
            sincosf(oph, &sn, &cs);
            int c = h * HDIM + d;
            g_ar[c * NPIX + qi] = omag * cs;
            g_ai[c * NPIX + qi] = omag * sn;
        }
    }
}

// ---------------- launch ----------------
extern "C" void kernel_launch(void* const* d_in, const int* in_sizes, int n_in,
                              void* d_out, int out_size)
{
    (void)in_sizes; (void)n_in; (void)out_size;
    const float* xr = (const float*)d_in[0];
    const float* xi = (const float*)d_in[1];
    float* out = (float*)d_out;

    const size_t O_OR  = 0;
    const size_t O_OI  = (size_t)CHN * NPIX;                  // 294912
    const size_t O_QKM = O_OI + (size_t)CHN * NPIX;           // 589824
    const size_t O_QKP = O_QKM + (size_t)NHEAD * NPIX * NPIX; // + 42467328

    dim3 cb(48, 8);
    dim3 cg(CHN / CO_T, IMGH);

    // q, k, v complex convs -> g_conv
    cconv_kernel<<<cg, cb>>>(xr, xi, (const float*)d_in[2],  (const float*)d_in[3],
                             (const float*)d_in[4],  (const float*)d_in[5],
                             nullptr, nullptr, 0, 0);
    cconv_kernel<<<cg, cb>>>(xr, xi, (const float*)d_in[6],  (const float*)d_in[7],
                             (const float*)d_in[8],  (const float*)d_in[9],
                             nullptr, nullptr, 0, 1);
    cconv_kernel<<<cg, cb>>>(xr, xi, (const float*)d_in[10], (const float*)d_in[11],
                             (const float*)d_in[12], (const float*)d_in[13],
                             nullptr, nullptr, 0, 2);

    // rotary + mag/phase into head layout
    {
        int tot = 3 * NHEAD * NPIX * (HDIM / 2);
        transform_kernel<<<(tot + 255) / 256, 256>>>();
    }

    // attention (writes qkm/qkp directly, a_r/a_i to scratch)
    attn_kernel<<<dim3(NPIX / NQ, NHEAD), 256>>>(out + O_QKM, out + O_QKP);

    // output complex conv: reads g_ar/g_ai, writes o_r/o_i
    cconv_kernel<<<cg, cb>>>(nullptr, nullptr, (const float*)d_in[14], (const float*)d_in[15],
                             (const float*)d_in[16], (const float*)d_in[17],
                             out + O_OR, out + O_OI, 1, 3);
}

// round 4
// speedup vs baseline: 1.4641x; 1.4641x over previous
#include <cuda_runtime.h>
#include <cstdint>
#include <cstddef>

#define CHN 128
#define IMGH 48
#define IMGW 48
#define NPIX 2304              // 48*48
#define NHEAD 8
#define HDIM 16

// ---------------- scratch (device globals; no allocation) ----------------
// g_head: qm,qp,km,kp,vm,vp in [h][n][16] layout
__device__ float g_head[6][CHN * NPIX];
__device__ float g_ar[CHN * NPIX];        // attention out real (c,n)
__device__ float g_ai[CHN * NPIX];        // attention out imag (c,n)

// invfreq[p] = 10000^(-2p/16) = 10^(-p/2)
__constant__ float c_invfreq[8] = {
    1.0f, 0.31622776601683794f, 0.1f, 0.031622776601683794f,
    0.01f, 0.0031622776601683794f, 0.001f, 0.00031622776601683794f
};

// ---------------- complex 3x3 conv (pad 1) + fused transform epilogue ----
// block (24, 8) = 192 threads; each thread: 2 pixels (tx, tx+24) x 2 co
// grid (CHN/16 = 8 co-blocks, 48 rows)
// mode: 0 = q (rotary+magphase -> g_head[0/1])
//       1 = k (rotary+magphase -> g_head[2/3])
//       2 = v (magphase        -> g_head[4/5])
//       3 = o (plain           -> yr_ext/yi_ext)
#define CO_T 16
#define CI_T 16

__global__ __launch_bounds__(192) void cconv_kernel(
    const float* __restrict__ xr_in, const float* __restrict__ xi_in,
    const float* __restrict__ wr, const float* __restrict__ wi,
    const float* __restrict__ br, const float* __restrict__ bi,
    float* __restrict__ yr_ext, float* __restrict__ yi_ext,
    int in_sel, int mode)
{
    __shared__ float xs_r[CI_T][3][IMGW + 2];
    __shared__ float xs_i[CI_T][3][IMGW + 2];
    __shared__ float ws_r[CO_T][CI_T][9];
    __shared__ float ws_i[CO_T][CI_T][9];

    const float* xr = in_sel ? g_ar : xr_in;
    const float* xi = in_sel ? g_ai : xi_in;

    const int tx = threadIdx.x;                // 0..23
    const int ty = threadIdx.y;                // 0..7
    const int y  = blockIdx.y;
    const int co0 = blockIdx.x * CO_T + ty * 2;
    const int tid = ty * 24 + tx;              // 0..191

    // acc[p][c] : p = pixel (tx, tx+24), c = co (co0, co0+1)
    float ar00=0.f, ar01=0.f, ar10=0.f, ar11=0.f;
    float ai00=0.f, ai01=0.f, ai10=0.f, ai11=0.f;

    for (int ci0 = 0; ci0 < CHN; ci0 += CI_T) {
        __syncthreads();
        // x tile: CI_T x 3 rows x 50 cols (zero-padded halo), both r & i
        for (int idx = tid; idx < CI_T * 3 * (IMGW + 2); idx += 192) {
            int ci  = idx / (3 * (IMGW + 2));
            int rem = idx % (3 * (IMGW + 2));
            int ry  = rem / (IMGW + 2);
            int rx  = rem % (IMGW + 2);
            int gy  = y + ry - 1;
            int gx  = rx - 1;
            float vr = 0.f, vi = 0.f;
            if ((unsigned)gy < (unsigned)IMGH && (unsigned)gx < (unsigned)IMGW) {
                int g = (ci0 + ci) * NPIX + gy * IMGW + gx;
                vr = xr[g]; vi = xi[g];
            }
            xs_r[ci][ry][rx] = vr;
            xs_i[ci][ry][rx] = vi;
        }
        // weights: CO_T x CI_T x 9
        for (int idx = tid; idx < CO_T * CI_T * 9; idx += 192) {
            int col = idx / (CI_T * 9);
            int rem = idx % (CI_T * 9);
            int ci  = rem / 9;
            int k   = rem % 9;
            int gw  = (blockIdx.x * CO_T + col) * (CHN * 9) + (ci0 + ci) * 9 + k;
            ws_r[col][ci][k] = wr[gw];
            ws_i[col][ci][k] = wi[gw];
        }
        __syncthreads();

        #pragma unroll 4
        for (int ci = 0; ci < CI_T; ci++) {
            // hoist weights for my 2 co into registers
            float w0r[9], w0i[9], w1r[9], w1i[9];
            #pragma unroll
            for (int k = 0; k < 9; k++) {
                w0r[k] = ws_r[ty * 2][ci][k];
                w0i[k] = ws_i[ty * 2][ci][k];
                w1r[k] = ws_r[ty * 2 + 1][ci][k];
                w1i[k] = ws_i[ty * 2 + 1][ci][k];
            }
            #pragma unroll
            for (int ky = 0; ky < 3; ky++) {
                #pragma unroll
                for (int kx = 0; kx < 3; kx++) {
                    const int k = ky * 3 + kx;
                    float xr0 = xs_r[ci][ky][tx + kx];
                    float xi0 = xs_i[ci][ky][tx + kx];
                    float xr1 = xs_r[ci][ky][tx + 24 + kx];
                    float xi1 = xs_i[ci][ky][tx + 24 + kx];
                    ar00 = fmaf(xr0, w0r[k], ar00); ar00 = fmaf(-xi0, w0i[k], ar00);
                    ai00 = fmaf(xr0, w0i[k], ai00); ai00 = fmaf( xi0, w0r[k], ai00);
                    ar01 = fmaf(xr0, w1r[k], ar01); ar01 = fmaf(-xi0, w1i[k], ar01);
                    ai01 = fmaf(xr0, w1i[k], ai01); ai01 = fmaf( xi0, w1r[k], ai01);
                    ar10 = fmaf(xr1, w0r[k], ar10); ar10 = fmaf(-xi1, w0i[k], ar10);
                    ai10 = fmaf(xr1, w0i[k], ai10); ai10 = fmaf( xi1, w0r[k], ai10);
                    ar11 = fmaf(xr1, w1r[k], ar11); ar11 = fmaf(-xi1, w1i[k], ar11);
                    ai11 = fmaf(xr1, w1i[k], ai11); ai11 = fmaf( xi1, w1r[k], ai11);
                }
            }
        }
    }

    const float br0 = br[co0],     br1 = br[co0 + 1];
    const float bi0 = bi[co0],     bi1 = bi[co0 + 1];

    if (mode == 3) {
        int n0 = y * IMGW + tx;
        yr_ext[co0 * NPIX + n0]            = ar00 + br0;
        yr_ext[(co0 + 1) * NPIX + n0]      = ar01 + br1;
        yi_ext[co0 * NPIX + n0]            = ai00 + bi0;
        yi_ext[(co0 + 1) * NPIX + n0]      = ai01 + bi1;
        int n1 = n0 + 24;
        yr_ext[co0 * NPIX + n1]            = ar10 + br0;
        yr_ext[(co0 + 1) * NPIX + n1]      = ar11 + br1;
        yi_ext[co0 * NPIX + n1]            = ai10 + bi0;
        yi_ext[(co0 + 1) * NPIX + n1]      = ai11 + bi1;
        return;
    }

    // fused transform: (optional rotary) + magnitude/phase into head layout
    const int h    = co0 >> 4;
    const int pair = (co0 >> 1) & 7;
    float* om = g_head[mode * 2];
    float* op = g_head[mode * 2 + 1];

    #pragma unroll
    for (int p = 0; p < 2; p++) {
        float r0 = (p ? ar10 : ar00) + br0;
        float r1 = (p ? ar11 : ar01) + br1;
        float i0 = (p ? ai10 : ai00) + bi0;
        float i1 = (p ? ai11 : ai01) + bi1;
        int n = y * IMGW + tx + p * 24;

        if (mode < 2) {
            float f = (float)n * c_invfreq[pair];
            float sn, cs;
            sincosf(f, &sn, &cs);
            float nr0 = r0 * cs - r1 * sn, nr1 = r1 * cs + r0 * sn;
            float ni0 = i0 * cs - i1 * sn, ni1 = i1 * cs + i0 * sn;
            r0 = nr0; r1 = nr1; i0 = ni0; i1 = ni1;
        }
        float m0 = sqrtf(r0 * r0 + i0 * i0), p0 = atan2f(i0, r0);
        float m1 = sqrtf(r1 * r1 + i1 * i1), p1 = atan2f(i1, r1);
        int base = (h * NPIX + n) * 16 + pair * 2;
        om[base] = m0; om[base + 1] = m1;
        op[base] = p0; op[base + 1] = p1;
    }
}

// ---------------- attention ----------------
// block: 512 threads = 128 q-rows x 4 key-splits; grid (18 q-tiles, 8 heads)
#define NQ 128
#define NSPLIT 4
#define TK 32
#define KPT (TK / NSPLIT)     // 8 keys per thread per tile
#define TKP 34                // score row stride (pool also used for reduction)

__global__ __launch_bounds__(512) void attn_kernel(
    float* __restrict__ qkm_o, float* __restrict__ qkp_o)
{
    __shared__ float km_s[TK][16], kp_s[TK][16], vm_s[TK][16], vp_s[TK][16];
    __shared__ float pool[2 * NQ * TKP];   // scores (mag|phase) / reduction buffer

    const int h  = blockIdx.y;
    const int q0 = blockIdx.x * NQ;
    const int t  = threadIdx.x;
    const int s  = t >> 7;          // key split 0..3
    const int r  = t & 127;         // q row in tile
    const int qi = q0 + r;
    const float scale = 0.14433756729740643f;   // 1/sqrt(48)

    float* sm_s = pool;                 // [NQ][TKP]
    float* sp_s = pool + NQ * TKP;      // [NQ][TKP]

    // load q row (mag + phase) into registers
    float qmr[16], qpr[16];
    {
        size_t base16 = ((size_t)(h * NPIX + qi)) * 16;
        #pragma unroll
        for (int d4 = 0; d4 < 4; d4++) {
            float4 a = ((const float4*)(g_head[0] + base16))[d4];
            float4 b = ((const float4*)(g_head[1] + base16))[d4];
            qmr[4*d4+0]=a.x; qmr[4*d4+1]=a.y; qmr[4*d4+2]=a.z; qmr[4*d4+3]=a.w;
            qpr[4*d4+0]=b.x; qpr[4*d4+1]=b.y; qpr[4*d4+2]=b.z; qpr[4*d4+3]=b.w;
        }
    }

    float mmax = -1e30f, lsum = 0.f;
    float am[16], ap[16];
    #pragma unroll
    for (int d = 0; d < 16; d++) { am[d] = 0.f; ap[d] = 0.f; }

    for (int kt = 0; kt < NPIX; kt += TK) {
        __syncthreads();
        // cooperative load of 32 keys (km,kp,vm,vp): 512 float4
        {
            int tn = t >> 7;           // tensor 0..3
            int ch = t & 127;          // float4 index in 32x16 tile
            size_t gbase = ((size_t)(h * NPIX + kt)) * 16;
            float4 v = ((const float4*)(g_head[2 + tn] + gbase))[ch];
            float4* dst = (tn == 0) ? (float4*)km_s :
                          (tn == 1) ? (float4*)kp_s :
                          (tn == 2) ? (float4*)vm_s : (float4*)vp_s;
            dst[ch] = v;
        }
        __syncthreads();

        // scores for my 8 keys
        float a_abs[KPT];
        float tmax = -1e30f;
        #pragma unroll
        for (int jj = 0; jj < KPT; jj++) {
            int j = s * KPT + jj;
            float dm = 0.f, dp = 0.f;
            #pragma unroll
            for (int d = 0; d < 16; d++) {
                dm = fmaf(qmr[d], km_s[j][d], dm);
                dp = fmaf(qpr[d], kp_s[j][d], dp);
            }
            float smv = dm * scale;
            float spv = dp * scale;
            sm_s[r * TKP + j] = smv;
            sp_s[r * TKP + j] = spv;
            a_abs[jj] = fabsf(smv);
            tmax = fmaxf(tmax, a_abs[jj]);
        }

        // tile-level online-softmax rescale (once per 8 keys)
        float nm = fmaxf(mmax, tmax);
        float corr = __expf(mmax - nm);
        lsum *= corr;
        #pragma unroll
        for (int d = 0; d < 16; d++) { am[d] *= corr; ap[d] *= corr; }
        mmax = nm;

        #pragma unroll
        for (int jj = 0; jj < KPT; jj++) {
            int j = s * KPT + jj;
            float p = __expf(a_abs[jj] - nm);
            lsum += p;
            #pragma unroll
            for (int d = 0; d < 16; d++) {
                am[d] = fmaf(p, vm_s[j][d], am[d]);
                ap[d] = fmaf(p, vp_s[j][d], ap[d]);
            }
        }
        __syncthreads();

        // coalesced writeout of score tile (both matrices), float2
        for (int i = t; i < NQ * (TK / 2); i += 512) {
            int row = i >> 4;               // 16 float2 per row
            int j2  = (i & 15) << 1;
            size_t g = ((size_t)h * NPIX + q0 + row) * NPIX + kt + j2;
            *(float2*)(qkm_o + g) = *(const float2*)&sm_s[row * TKP + j2];
            *(float2*)(qkp_o + g) = *(const float2*)&sp_s[row * TKP + j2];
        }
    }

    // ---- reduce 4 splits per q row (2 pairwise rounds via pool) ----
    __syncthreads();
    // round A: splits 2,3 publish (m, l, am[16], ap[16]) = 34 floats
    if (s >= 2) {
        float* dst = pool + ((s - 2) * NQ + r) * TKP;
        dst[0] = mmax; dst[1] = lsum;
        #pragma unroll
        for (int d = 0; d < 16; d++) { dst[2 + d] = am[d]; dst[18 + d] = ap[d]; }
    }
    __syncthreads();
    if (s < 2) {
        const float* src = pool + (s * NQ + r) * TKP;
        float m2 = src[0], l2 = src[1];
        float M  = fmaxf(mmax, m2);
        float c0 = __expf(mmax - M), c1 = __expf(m2 - M);
        lsum = lsum * c0 + l2 * c1;
        #pragma unroll
        for (int d = 0; d < 16; d++) {
            am[d] = am[d] * c0 + src[2 + d]  * c1;
            ap[d] = ap[d] * c0 + src[18 + d] * c1;
        }
        mmax = M;
    }
    __syncthreads();
    // round B: split 1 publishes
    if (s == 1) {
        float* dst = pool + r * TKP;
        dst[0] = mmax; dst[1] = lsum;
        #pragma unroll
        for (int d = 0; d < 16; d++) { dst[2 + d] = am[d]; dst[18 + d] = ap[d]; }
    }
    __syncthreads();
    if (s == 0) {
        const float* src = pool + r * TKP;
        float m2 = src[0], l2 = src[1];
        float M  = fmaxf(mmax, m2);
        float c0 = __expf(mmax - M), c1 = __expf(m2 - M);
        float L  = lsum * c0 + l2 * c1;
        float invL = 1.f / L;
        #pragma unroll
        for (int d = 0; d < 16; d++) {
            float omag = (am[d] * c0 + src[2 + d]  * c1) * invL;
            float oph  = (ap[d] * c0 + src[18 + d] * c1) * invL;
            float sn, cs;
            sincosf(oph, &sn, &cs);
            int c = h * HDIM + d;
            g_ar[c * NPIX + qi] = omag * cs;
            g_ai[c * NPIX + qi] = omag * sn;
        }
    }
}

// ---------------- launch ----------------
extern "C" void kernel_launch(void* const* d_in, const int* in_sizes, int n_in,
                              void* d_out, int out_size)
{
    (void)in_sizes; (void)n_in; (void)out_size;
    const float* xr = (const float*)d_in[0];
    const float* xi = (const float*)d_in[1];
    float* out = (float*)d_out;

    const size_t O_OR  = 0;
    const size_t O_OI  = (size_t)CHN * NPIX;                  // 294912
    const size_t O_QKM = O_OI + (size_t)CHN * NPIX;           // 589824
    const size_t O_QKP = O_QKM + (size_t)NHEAD * NPIX * NPIX;

    dim3 cb(24, 8);
    dim3 cg(CHN / CO_T, IMGH);

    // q, k, v complex convs with fused rotary/magphase epilogue -> g_head
    cconv_kernel<<<cg, cb>>>(xr, xi, (const float*)d_in[2],  (const float*)d_in[3],
                             (const float*)d_in[4],  (const float*)d_in[5],
                             nullptr, nullptr, 0, 0);
    cconv_kernel<<<cg, cb>>>(xr, xi, (const float*)d_in[6],  (const float*)d_in[7],
                             (const float*)d_in[8],  (const float*)d_in[9],
                             nullptr, nullptr, 0, 1);
    cconv_kernel<<<cg, cb>>>(xr, xi, (const float*)d_in[10], (const float*)d_in[11],
                             (const float*)d_in[12], (const float*)d_in[13],
                             nullptr, nullptr, 0, 2);

    // attention (writes qkm/qkp directly, a_r/a_i to scratch)
    attn_kernel<<<dim3(NPIX / NQ, NHEAD), 512>>>(out + O_QKM, out + O_QKP);

    // output complex conv: reads g_ar/g_ai, writes o_r/o_i
    cconv_kernel<<<cg, cb>>>(nullptr, nullptr, (const float*)d_in[14], (const float*)d_in[15],
                             (const float*)d_in[16], (const float*)d_in[17],
                             out + O_OR, out + O_OI, 1, 3);
}

// round 5
// speedup vs baseline: 1.5164x; 1.0357x over previous
#include <cuda_runtime.h>
#include <cstdint>
#include <cstddef>

#define CHN 128
#define IMGH 48
#define IMGW 48
#define NPIX 2304              // 48*48
#define NHEAD 8
#define HDIM 16

// ---------------- scratch (device globals; no allocation) ----------------
// g_head: qm,qp,km,kp,vm,vp in [h][n][16] layout
__device__ float g_head[6][CHN * NPIX];
__device__ float g_ar[CHN * NPIX];        // attention out real (c,n)
__device__ float g_ai[CHN * NPIX];        // attention out imag (c,n)

// invfreq[p] = 10000^(-2p/16) = 10^(-p/2)
__constant__ float c_invfreq[8] = {
    1.0f, 0.31622776601683794f, 0.1f, 0.031622776601683794f,
    0.01f, 0.0031622776601683794f, 0.001f, 0.00031622776601683794f
};

// ---------------- complex 3x3 conv (pad 1) + fused transform epilogue ----
// block (24, 8) = 192 threads; each thread: 2 CONTIGUOUS pixels (2tx,2tx+1) x 2 co
// grid (CHN/16 = 8 co-blocks, 48 rows)
// mode: 0 = q (rotary+magphase -> g_head[0/1])
//       1 = k (rotary+magphase -> g_head[2/3])
//       2 = v (magphase        -> g_head[4/5])
//       3 = o (plain           -> yr_ext/yi_ext)
#define CO_T 16
#define CI_T 16
#define WPAD 12                 // padded filter stride for float4 loads

__global__ __launch_bounds__(192) void cconv_kernel(
    const float* __restrict__ xr_in, const float* __restrict__ xi_in,
    const float* __restrict__ wr, const float* __restrict__ wi,
    const float* __restrict__ br, const float* __restrict__ bi,
    float* __restrict__ yr_ext, float* __restrict__ yi_ext,
    int in_sel, int mode)
{
    __shared__ float xs_r[CI_T][3][IMGW + 4];   // 52 cols: 16B-aligned rows
    __shared__ float xs_i[CI_T][3][IMGW + 4];
    __shared__ float ws_r[CO_T][CI_T][WPAD];
    __shared__ float ws_i[CO_T][CI_T][WPAD];

    const float* xr = in_sel ? g_ar : xr_in;
    const float* xi = in_sel ? g_ai : xi_in;

    const int tx = threadIdx.x;                // 0..23
    const int ty = threadIdx.y;                // 0..7
    const int y  = blockIdx.y;
    const int co0 = blockIdx.x * CO_T + ty * 2;
    const int tid = ty * 24 + tx;              // 0..191
    const int px0 = tx * 2;                    // first of pixel pair

    // acc[p][c] : p = pixel (px0, px0+1), c = co (co0, co0+1)
    float ar00=0.f, ar01=0.f, ar10=0.f, ar11=0.f;
    float ai00=0.f, ai01=0.f, ai10=0.f, ai11=0.f;

    for (int ci0 = 0; ci0 < CHN; ci0 += CI_T) {
        __syncthreads();
        // x tile: CI_T x 3 rows x 50 used cols (zero-padded halo), both r & i
        for (int idx = tid; idx < CI_T * 3 * (IMGW + 2); idx += 192) {
            int ci  = idx / (3 * (IMGW + 2));
            int rem = idx % (3 * (IMGW + 2));
            int ry  = rem / (IMGW + 2);
            int rx  = rem % (IMGW + 2);
            int gy  = y + ry - 1;
            int gx  = rx - 1;
            float vr = 0.f, vi = 0.f;
            if ((unsigned)gy < (unsigned)IMGH && (unsigned)gx < (unsigned)IMGW) {
                int g = (ci0 + ci) * NPIX + gy * IMGW + gx;
                vr = xr[g]; vi = xi[g];
            }
            xs_r[ci][ry][rx] = vr;
            xs_i[ci][ry][rx] = vi;
        }
        // weights: CO_T x CI_T x 9 into padded stride-12 layout
        for (int idx = tid; idx < CO_T * CI_T * 9; idx += 192) {
            int col = idx / (CI_T * 9);
            int rem = idx % (CI_T * 9);
            int ci  = rem / 9;
            int k   = rem % 9;
            int gw  = (blockIdx.x * CO_T + col) * (CHN * 9) + (ci0 + ci) * 9 + k;
            ws_r[col][ci][k] = wr[gw];
            ws_i[col][ci][k] = wi[gw];
        }
        __syncthreads();

        #pragma unroll 4
        for (int ci = 0; ci < CI_T; ci++) {
            // hoist weights for my 2 co via float4 (stride-12 layout, 16B aligned)
            float w0r[9], w0i[9], w1r[9], w1i[9];
            {
                const float4* p;
                float4 t;
                p = (const float4*)ws_r[ty * 2][ci];
                t = p[0]; w0r[0]=t.x; w0r[1]=t.y; w0r[2]=t.z; w0r[3]=t.w;
                t = p[1]; w0r[4]=t.x; w0r[5]=t.y; w0r[6]=t.z; w0r[7]=t.w;
                t = p[2]; w0r[8]=t.x;
                p = (const float4*)ws_i[ty * 2][ci];
                t = p[0]; w0i[0]=t.x; w0i[1]=t.y; w0i[2]=t.z; w0i[3]=t.w;
                t = p[1]; w0i[4]=t.x; w0i[5]=t.y; w0i[6]=t.z; w0i[7]=t.w;
                t = p[2]; w0i[8]=t.x;
                p = (const float4*)ws_r[ty * 2 + 1][ci];
                t = p[0]; w1r[0]=t.x; w1r[1]=t.y; w1r[2]=t.z; w1r[3]=t.w;
                t = p[1]; w1r[4]=t.x; w1r[5]=t.y; w1r[6]=t.z; w1r[7]=t.w;
                t = p[2]; w1r[8]=t.x;
                p = (const float4*)ws_i[ty * 2 + 1][ci];
                t = p[0]; w1i[0]=t.x; w1i[1]=t.y; w1i[2]=t.z; w1i[3]=t.w;
                t = p[1]; w1i[4]=t.x; w1i[5]=t.y; w1i[6]=t.z; w1i[7]=t.w;
                t = p[2]; w1i[8]=t.x;
            }
            #pragma unroll
            for (int ky = 0; ky < 3; ky++) {
                // 4 consecutive values cover both pixels' 3 taps (float2 loads)
                float2 ra = *(const float2*)&xs_r[ci][ky][px0];
                float2 rb = *(const float2*)&xs_r[ci][ky][px0 + 2];
                float2 ia = *(const float2*)&xs_i[ci][ky][px0];
                float2 ib = *(const float2*)&xs_i[ci][ky][px0 + 2];
                float xr0t[3] = { ra.x, ra.y, rb.x };   // pixel0 taps
                float xr1t[3] = { ra.y, rb.x, rb.y };   // pixel1 taps
                float xi0t[3] = { ia.x, ia.y, ib.x };
                float xi1t[3] = { ia.y, ib.x, ib.y };
                #pragma unroll
                for (int kx = 0; kx < 3; kx++) {
                    const int k = ky * 3 + kx;
                    float xr0 = xr0t[kx], xi0 = xi0t[kx];
                    float xr1 = xr1t[kx], xi1 = xi1t[kx];
                    ar00 = fmaf(xr0, w0r[k], ar00); ar00 = fmaf(-xi0, w0i[k], ar00);
                    ai00 = fmaf(xr0, w0i[k], ai00); ai00 = fmaf( xi0, w0r[k], ai00);
                    ar01 = fmaf(xr0, w1r[k], ar01); ar01 = fmaf(-xi0, w1i[k], ar01);
                    ai01 = fmaf(xr0, w1i[k], ai01); ai01 = fmaf( xi0, w1r[k], ai01);
                    ar10 = fmaf(xr1, w0r[k], ar10); ar10 = fmaf(-xi1, w0i[k], ar10);
                    ai10 = fmaf(xr1, w0i[k], ai10); ai10 = fmaf( xi1, w0r[k], ai10);
                    ar11 = fmaf(xr1, w1r[k], ar11); ar11 = fmaf(-xi1, w1i[k], ar11);
                    ai11 = fmaf(xr1, w1i[k], ai11); ai11 = fmaf( xi1, w1r[k], ai11);
                }
            }
        }
    }

    const float br0 = br[co0],     br1 = br[co0 + 1];
    const float bi0 = bi[co0],     bi1 = bi[co0 + 1];

    if (mode == 3) {
        int n0 = y * IMGW + px0;
        yr_ext[co0 * NPIX + n0]           = ar00 + br0;
        yr_ext[co0 * NPIX + n0 + 1]       = ar10 + br0;
        yr_ext[(co0 + 1) * NPIX + n0]     = ar01 + br1;
        yr_ext[(co0 + 1) * NPIX + n0 + 1] = ar11 + br1;
        yi_ext[co0 * NPIX + n0]           = ai00 + bi0;
        yi_ext[co0 * NPIX + n0 + 1]       = ai10 + bi0;
        yi_ext[(co0 + 1) * NPIX + n0]     = ai01 + bi1;
        yi_ext[(co0 + 1) * NPIX + n0 + 1] = ai11 + bi1;
        return;
    }

    // fused transform: (optional rotary) + magnitude/phase into head layout
    const int h    = co0 >> 4;
    const int pair = (co0 >> 1) & 7;
    float* om = g_head[mode * 2];
    float* op = g_head[mode * 2 + 1];

    #pragma unroll
    for (int p = 0; p < 2; p++) {
        float r0 = (p ? ar10 : ar00) + br0;
        float r1 = (p ? ar11 : ar01) + br1;
        float i0 = (p ? ai10 : ai00) + bi0;
        float i1 = (p ? ai11 : ai01) + bi1;
        int n = y * IMGW + px0 + p;

        if (mode < 2) {
            float f = (float)n * c_invfreq[pair];
            float sn, cs;
            sincosf(f, &sn, &cs);
            float nr0 = r0 * cs - r1 * sn, nr1 = r1 * cs + r0 * sn;
            float ni0 = i0 * cs - i1 * sn, ni1 = i1 * cs + i0 * sn;
            r0 = nr0; r1 = nr1; i0 = ni0; i1 = ni1;
        }
        float m0 = sqrtf(r0 * r0 + i0 * i0), p0 = atan2f(i0, r0);
        float m1 = sqrtf(r1 * r1 + i1 * i1), p1 = atan2f(i1, r1);
        int base = (h * NPIX + n) * 16 + pair * 2;
        om[base] = m0; om[base + 1] = m1;
        op[base] = p0; op[base + 1] = p1;
    }
}

// ---------------- attention ----------------
// block: 512 threads = 128 q-rows x 4 key-splits; grid (18 q-tiles, 8 heads)
#define NQ 128
#define NSPLIT 4
#define TK 32
#define KPT (TK / NSPLIT)     // 8 keys per thread per tile
#define TKP 34                // score row stride (pool also used for reduction)

__global__ __launch_bounds__(512) void attn_kernel(
    float* __restrict__ qkm_o, float* __restrict__ qkp_o)
{
    __shared__ float4 km4[TK][4], kp4[TK][4], vm4[TK][4], vp4[TK][4];
    __shared__ float pool[2 * NQ * TKP];   // scores (mag|phase) / reduction buffer

    const int h  = blockIdx.y;
    const int q0 = blockIdx.x * NQ;
    const int t  = threadIdx.x;
    const int s  = t >> 7;          // key split 0..3
    const int r  = t & 127;         // q row in tile
    const int qi = q0 + r;
    const float scale = 0.14433756729740643f;   // 1/sqrt(48)

    float* sm_s = pool;                 // [NQ][TKP]
    float* sp_s = pool + NQ * TKP;      // [NQ][TKP]

    // load q row (mag + phase) into registers as float4s
    float4 qm[4], qp[4];
    {
        size_t base16 = ((size_t)(h * NPIX + qi)) * 16;
        #pragma unroll
        for (int d4 = 0; d4 < 4; d4++) {
            qm[d4] = ((const float4*)(g_head[0] + base16))[d4];
            qp[d4] = ((const float4*)(g_head[1] + base16))[d4];
        }
    }

    float mmax = -1e30f, lsum = 0.f;
    float am[16], ap[16];
    #pragma unroll
    for (int d = 0; d < 16; d++) { am[d] = 0.f; ap[d] = 0.f; }

    for (int kt = 0; kt < NPIX; kt += TK) {
        __syncthreads();
        // cooperative load of 32 keys (km,kp,vm,vp): 512 float4
        {
            int tn = t >> 7;           // tensor 0..3
            int ch = t & 127;          // float4 index in 32x16 tile
            size_t gbase = ((size_t)(h * NPIX + kt)) * 16;
            float4 v = ((const float4*)(g_head[2 + tn] + gbase))[ch];
            float4* dst = (tn == 0) ? (float4*)km4 :
                          (tn == 1) ? (float4*)kp4 :
                          (tn == 2) ? (float4*)vm4 : (float4*)vp4;
            dst[ch] = v;
        }
        __syncthreads();

        // scores for my 8 keys (all smem reads are broadcast LDS.128)
        float a_abs[KPT];
        float tmax = -1e30f;
        #pragma unroll
        for (int jj = 0; jj < KPT; jj++) {
            int j = s * KPT + jj;
            float dm = 0.f, dp = 0.f;
            #pragma unroll
            for (int d4 = 0; d4 < 4; d4++) {
                float4 kv = km4[j][d4];
                dm = fmaf(qm[d4].x, kv.x, dm); dm = fmaf(qm[d4].y, kv.y, dm);
                dm = fmaf(qm[d4].z, kv.z, dm); dm = fmaf(qm[d4].w, kv.w, dm);
                float4 pv = kp4[j][d4];
                dp = fmaf(qp[d4].x, pv.x, dp); dp = fmaf(qp[d4].y, pv.y, dp);
                dp = fmaf(qp[d4].z, pv.z, dp); dp = fmaf(qp[d4].w, pv.w, dp);
            }
            float smv = dm * scale;
            float spv = dp * scale;
            sm_s[r * TKP + j] = smv;
            sp_s[r * TKP + j] = spv;
            a_abs[jj] = fabsf(smv);
            tmax = fmaxf(tmax, a_abs[jj]);
        }

        // tile-level online-softmax rescale (once per 8 keys)
        float nm = fmaxf(mmax, tmax);
        float corr = __expf(mmax - nm);
        lsum *= corr;
        #pragma unroll
        for (int d = 0; d < 16; d++) { am[d] *= corr; ap[d] *= corr; }
        mmax = nm;

        #pragma unroll
        for (int jj = 0; jj < KPT; jj++) {
            int j = s * KPT + jj;
            float p = __expf(a_abs[jj] - nm);
            lsum += p;
            #pragma unroll
            for (int d4 = 0; d4 < 4; d4++) {
                float4 vv = vm4[j][d4];
                am[d4*4+0] = fmaf(p, vv.x, am[d4*4+0]);
                am[d4*4+1] = fmaf(p, vv.y, am[d4*4+1]);
                am[d4*4+2] = fmaf(p, vv.z, am[d4*4+2]);
                am[d4*4+3] = fmaf(p, vv.w, am[d4*4+3]);
                float4 pv = vp4[j][d4];
                ap[d4*4+0] = fmaf(p, pv.x, ap[d4*4+0]);
                ap[d4*4+1] = fmaf(p, pv.y, ap[d4*4+1]);
                ap[d4*4+2] = fmaf(p, pv.z, ap[d4*4+2]);
                ap[d4*4+3] = fmaf(p, pv.w, ap[d4*4+3]);
            }
        }
        __syncthreads();

        // coalesced writeout of score tile (both matrices), float2
        for (int i = t; i < NQ * (TK / 2); i += 512) {
            int row = i >> 4;               // 16 float2 per row
            int j2  = (i & 15) << 1;
            size_t g = ((size_t)h * NPIX + q0 + row) * NPIX + kt + j2;
            *(float2*)(qkm_o + g) = *(const float2*)&sm_s[row * TKP + j2];
            *(float2*)(qkp_o + g) = *(const float2*)&sp_s[row * TKP + j2];
        }
    }

    // ---- reduce 4 splits per q row (2 pairwise rounds via pool) ----
    __syncthreads();
    // round A: splits 2,3 publish (m, l, am[16], ap[16]) = 34 floats
    if (s >= 2) {
        float* dst = pool + ((s - 2) * NQ + r) * TKP;
        dst[0] = mmax; dst[1] = lsum;
        #pragma unroll
        for (int d = 0; d < 16; d++) { dst[2 + d] = am[d]; dst[18 + d] = ap[d]; }
    }
    __syncthreads();
    if (s < 2) {
        const float* src = pool + (s * NQ + r) * TKP;
        float m2 = src[0], l2 = src[1];
        float M  = fmaxf(mmax, m2);
        float c0 = __expf(mmax - M), c1 = __expf(m2 - M);
        lsum = lsum * c0 + l2 * c1;
        #pragma unroll
        for (int d = 0; d < 16; d++) {
            am[d] = am[d] * c0 + src[2 + d]  * c1;
            ap[d] = ap[d] * c0 + src[18 + d] * c1;
        }
        mmax = M;
    }
    __syncthreads();
    // round B: split 1 publishes
    if (s == 1) {
        float* dst = pool + r * TKP;
        dst[0] = mmax; dst[1] = lsum;
        #pragma unroll
        for (int d = 0; d < 16; d++) { dst[2 + d] = am[d]; dst[18 + d] = ap[d]; }
    }
    __syncthreads();
    if (s == 0) {
        const float* src = pool + r * TKP;
        float m2 = src[0], l2 = src[1];
        float M  = fmaxf(mmax, m2);
        float c0 = __expf(mmax - M), c1 = __expf(m2 - M);
        float L  = lsum * c0 + l2 * c1;
        float invL = 1.f / L;
        #pragma unroll
        for (int d = 0; d < 16; d++) {
            float omag = (am[d] * c0 + src[2 + d]  * c1) * invL;
            float oph  = (ap[d] * c0 + src[18 + d] * c1) * invL;
            float sn, cs;
            sincosf(oph, &sn, &cs);
            int c = h * HDIM + d;
            g_ar[c * NPIX + qi] = omag * cs;
            g_ai[c * NPIX + qi] = omag * sn;
        }
    }
}

// ---------------- launch ----------------
extern "C" void kernel_launch(void* const* d_in, const int* in_sizes, int n_in,
                              void* d_out, int out_size)
{
    (void)in_sizes; (void)n_in; (void)out_size;
    const float* xr = (const float*)d_in[0];
    const float* xi = (const float*)d_in[1];
    float* out = (float*)d_out;

    const size_t O_OR  = 0;
    const size_t O_OI  = (size_t)CHN * NPIX;                  // 294912
    const size_t O_QKM = O_OI + (size_t)CHN * NPIX;           // 589824
    const size_t O_QKP = O_QKM + (size_t)NHEAD * NPIX * NPIX;

    dim3 cb(24, 8);
    dim3 cg(CHN / CO_T, IMGH);

    // q, k, v complex convs with fused rotary/magphase epilogue -> g_head
    cconv_kernel<<<cg, cb>>>(xr, xi, (const float*)d_in[2],  (const float*)d_in[3],
                             (const float*)d_in[4],  (const float*)d_in[5],
                             nullptr, nullptr, 0, 0);
    cconv_kernel<<<cg, cb>>>(xr, xi, (const float*)d_in[6],  (const float*)d_in[7],
                             (const float*)d_in[8],  (const float*)d_in[9],
                             nullptr, nullptr, 0, 1);
    cconv_kernel<<<cg, cb>>>(xr, xi, (const float*)d_in[10], (const float*)d_in[11],
                             (const float*)d_in[12], (const float*)d_in[13],
                             nullptr, nullptr, 0, 2);

    // attention (writes qkm/qkp directly, a_r/a_i to scratch)
    attn_kernel<<<dim3(NPIX / NQ, NHEAD), 512>>>(out + O_QKM, out + O_QKP);

    // output complex conv: reads g_ar/g_ai, writes o_r/o_i
    cconv_kernel<<<cg, cb>>>(nullptr, nullptr, (const float*)d_in[14], (const float*)d_in[15],
                             (const float*)d_in[16], (const float*)d_in[17],
                             out + O_OR, out + O_OI, 1, 3);
}

// round 6
// speedup vs baseline: 1.7032x; 1.1232x over previous
#include <cuda_runtime.h>
#include <cstdint>
#include <cstddef>

#define CHN 128
#define IMGH 48
#define IMGW 48
#define NPIX 2304              // 48*48
#define NHEAD 8
#define HDIM 16

typedef unsigned long long u64t;

// ---------------- f32x2 packed helpers (sm_103a) ----------------
__device__ __forceinline__ u64t pack2(float lo, float hi) {
    u64t d;
    asm("mov.b64 %0, {%1, %2};" : "=l"(d) : "r"(__float_as_uint(lo)), "r"(__float_as_uint(hi)));
    return d;
}
__device__ __forceinline__ u64t pack2s(float v) {
    u64t d;
    unsigned int u = __float_as_uint(v);
    asm("mov.b64 %0, {%1, %1};" : "=l"(d) : "r"(u));
    return d;
}
__device__ __forceinline__ void unpack2(u64t v, float& lo, float& hi) {
    unsigned int a, b;
    asm("mov.b64 {%0, %1}, %2;" : "=r"(a), "=r"(b) : "l"(v));
    lo = __uint_as_float(a); hi = __uint_as_float(b);
}
__device__ __forceinline__ u64t ffma2(u64t a, u64t b, u64t c) {
    u64t d;
    asm("fma.rn.f32x2 %0, %1, %2, %3;" : "=l"(d) : "l"(a), "l"(b), "l"(c));
    return d;
}
__device__ __forceinline__ u64t fmul2(u64t a, u64t b) {
    u64t d;
    asm("mul.rn.f32x2 %0, %1, %2;" : "=l"(d) : "l"(a), "l"(b));
    return d;
}
__device__ __forceinline__ u64t fadd2(u64t a, u64t b) {
    u64t d;
    asm("add.rn.f32x2 %0, %1, %2;" : "=l"(d) : "l"(a), "l"(b));
    return d;
}

// ---------------- scratch (device globals; no allocation) ----------------
// q/k/v in head layout, interleaved pairs: [h][n][d][{mag,phase}] (32 floats/row)
__device__ float g_q[2 * CHN * NPIX];
__device__ float g_k[2 * CHN * NPIX];
__device__ float g_v[2 * CHN * NPIX];
__device__ float g_ar[CHN * NPIX];        // attention out real (c,n)
__device__ float g_ai[CHN * NPIX];        // attention out imag (c,n)

// invfreq[p] = 10000^(-2p/16) = 10^(-p/2)
__constant__ float c_invfreq[8] = {
    1.0f, 0.31622776601683794f, 0.1f, 0.031622776601683794f,
    0.01f, 0.0031622776601683794f, 0.001f, 0.00031622776601683794f
};

// ---------------- complex 3x3 conv (pad 1), f32x2 inner loop ----------------
// block (24, 8) = 192 threads; each thread: 2 contiguous pixels x 2 co (a pair)
// grid (CHN/16 = 8 co-blocks, 48 rows)
// mode: 0=q (rotary+magphase -> g_q), 1=k (-> g_k), 2=v (no rotary -> g_v),
//       3=o (plain -> yr_ext/yi_ext)
#define CO_T 16
#define CI_T 16

__global__ __launch_bounds__(192) void cconv_kernel(
    const float* __restrict__ xr_in, const float* __restrict__ xi_in,
    const float* __restrict__ wr, const float* __restrict__ wi,
    const float* __restrict__ br, const float* __restrict__ bi,
    float* __restrict__ yr_ext, float* __restrict__ yi_ext,
    int in_sel, int mode)
{
    __shared__ float xs_r[CI_T][3][IMGW + 4];   // rows 16B-aligned
    __shared__ float xs_i[CI_T][3][IMGW + 4];
    __shared__ float ws_r[CI_T][9][CO_T];       // co fastest -> co-pair LDS.64
    __shared__ float ws_i[CI_T][9][CO_T];

    const float* xr = in_sel ? g_ar : xr_in;
    const float* xi = in_sel ? g_ai : xi_in;

    const int tx = threadIdx.x;                // 0..23
    const int ty = threadIdx.y;                // 0..7
    const int y  = blockIdx.y;
    const int co0 = blockIdx.x * CO_T + ty * 2;
    const int tid = ty * 24 + tx;              // 0..191
    const int px0 = tx * 2;                    // first of pixel pair

    // packed accumulators over co pair: s_xy = sum of x-part * y-weight
    u64t s_rr0 = 0, s_ii0 = 0, s_ri0 = 0, s_ir0 = 0;   // pixel 0
    u64t s_rr1 = 0, s_ii1 = 0, s_ri1 = 0, s_ir1 = 0;   // pixel 1

    for (int ci0 = 0; ci0 < CHN; ci0 += CI_T) {
        __syncthreads();
        // x tile: CI_T x 3 rows x 50 used cols (zero-padded halo)
        for (int idx = tid; idx < CI_T * 3 * (IMGW + 2); idx += 192) {
            int ci  = idx / (3 * (IMGW + 2));
            int rem = idx % (3 * (IMGW + 2));
            int ry  = rem / (IMGW + 2);
            int rx  = rem % (IMGW + 2);
            int gy  = y + ry - 1;
            int gx  = rx - 1;
            float vr = 0.f, vi = 0.f;
            if ((unsigned)gy < (unsigned)IMGH && (unsigned)gx < (unsigned)IMGW) {
                int g = (ci0 + ci) * NPIX + gy * IMGW + gx;
                vr = xr[g]; vi = xi[g];
            }
            xs_r[ci][ry][rx] = vr;
            xs_i[ci][ry][rx] = vi;
        }
        // weights into [ci][k][co] layout (k fastest in gmem read -> coalesced)
        for (int idx = tid; idx < CO_T * CI_T * 9; idx += 192) {
            int k   = idx % 9;
            int col = (idx / 9) % CO_T;
            int ci  = idx / (9 * CO_T);
            int gw  = (blockIdx.x * CO_T + col) * (CHN * 9) + (ci0 + ci) * 9 + k;
            ws_r[ci][k][col] = wr[gw];
            ws_i[ci][k][col] = wi[gw];
        }
        __syncthreads();

        #pragma unroll 2
        for (int ci = 0; ci < CI_T; ci++) {
            // hoist my co-pair weights as packed u64 (aligned LDS.64)
            u64t wrp[9], wip[9];
            #pragma unroll
            for (int k = 0; k < 9; k++) {
                wrp[k] = *(const u64t*)&ws_r[ci][k][ty * 2];
                wip[k] = *(const u64t*)&ws_i[ci][k][ty * 2];
            }
            #pragma unroll
            for (int ky = 0; ky < 3; ky++) {
                float2 ra = *(const float2*)&xs_r[ci][ky][px0];
                float2 rb = *(const float2*)&xs_r[ci][ky][px0 + 2];
                float2 ia = *(const float2*)&xs_i[ci][ky][px0];
                float2 ib = *(const float2*)&xs_i[ci][ky][px0 + 2];
                float xr0t[3] = { ra.x, ra.y, rb.x };   // pixel0 taps
                float xr1t[3] = { ra.y, rb.x, rb.y };   // pixel1 taps
                float xi0t[3] = { ia.x, ia.y, ib.x };
                float xi1t[3] = { ia.y, ib.x, ib.y };
                #pragma unroll
                for (int kx = 0; kx < 3; kx++) {
                    const int k = ky * 3 + kx;
                    u64t xr0p = pack2s(xr0t[kx]);
                    u64t xi0p = pack2s(xi0t[kx]);
                    u64t xr1p = pack2s(xr1t[kx]);
                    u64t xi1p = pack2s(xi1t[kx]);
                    s_rr0 = ffma2(xr0p, wrp[k], s_rr0);
                    s_ii0 = ffma2(xi0p, wip[k], s_ii0);
                    s_ri0 = ffma2(xr0p, wip[k], s_ri0);
                    s_ir0 = ffma2(xi0p, wrp[k], s_ir0);
                    s_rr1 = ffma2(xr1p, wrp[k], s_rr1);
                    s_ii1 = ffma2(xi1p, wip[k], s_ii1);
                    s_ri1 = ffma2(xr1p, wip[k], s_ri1);
                    s_ir1 = ffma2(xi1p, wrp[k], s_ir1);
                }
            }
        }
    }

    // unpack and combine: ar = sum(xr*wr) - sum(xi*wi); ai = sum(xr*wi) + sum(xi*wr)
    float rr0l, rr0h, ii0l, ii0h, ri0l, ri0h, ir0l, ir0h;
    float rr1l, rr1h, ii1l, ii1h, ri1l, ri1h, ir1l, ir1h;
    unpack2(s_rr0, rr0l, rr0h); unpack2(s_ii0, ii0l, ii0h);
    unpack2(s_ri0, ri0l, ri0h); unpack2(s_ir0, ir0l, ir0h);
    unpack2(s_rr1, rr1l, rr1h); unpack2(s_ii1, ii1l, ii1h);
    unpack2(s_ri1, ri1l, ri1h); unpack2(s_ir1, ir1l, ir1h);

    float ar00 = rr0l - ii0l, ar01 = rr0h - ii0h;
    float ai00 = ri0l + ir0l, ai01 = ri0h + ir0h;
    float ar10 = rr1l - ii1l, ar11 = rr1h - ii1h;
    float ai10 = ri1l + ir1l, ai11 = ri1h + ir1h;

    const float br0 = br[co0], br1 = br[co0 + 1];
    const float bi0 = bi[co0], bi1 = bi[co0 + 1];

    if (mode == 3) {
        int n0 = y * IMGW + px0;
        yr_ext[co0 * NPIX + n0]           = ar00 + br0;
        yr_ext[co0 * NPIX + n0 + 1]       = ar10 + br0;
        yr_ext[(co0 + 1) * NPIX + n0]     = ar01 + br1;
        yr_ext[(co0 + 1) * NPIX + n0 + 1] = ar11 + br1;
        yi_ext[co0 * NPIX + n0]           = ai00 + bi0;
        yi_ext[co0 * NPIX + n0 + 1]       = ai10 + bi0;
        yi_ext[(co0 + 1) * NPIX + n0]     = ai01 + bi1;
        yi_ext[(co0 + 1) * NPIX + n0 + 1] = ai11 + bi1;
        return;
    }

    // fused transform: (optional rotary) + magnitude/phase, interleaved pairs
    const int h    = co0 >> 4;
    const int pair = (co0 >> 1) & 7;
    float* gp = (mode == 0) ? g_q : (mode == 1) ? g_k : g_v;

    #pragma unroll
    for (int p = 0; p < 2; p++) {
        float r0 = (p ? ar10 : ar00) + br0;
        float r1 = (p ? ar11 : ar01) + br1;
        float i0 = (p ? ai10 : ai00) + bi0;
        float i1 = (p ? ai11 : ai01) + bi1;
        int n = y * IMGW + px0 + p;

        if (mode < 2) {
            float f = (float)n * c_invfreq[pair];
            float sn, cs;
            sincosf(f, &sn, &cs);
            float nr0 = r0 * cs - r1 * sn, nr1 = r1 * cs + r0 * sn;
            float ni0 = i0 * cs - i1 * sn, ni1 = i1 * cs + i0 * sn;
            r0 = nr0; r1 = nr1; i0 = ni0; i1 = ni1;
        }
        float m0 = sqrtf(r0 * r0 + i0 * i0), p0 = atan2f(i0, r0);
        float m1 = sqrtf(r1 * r1 + i1 * i1), p1 = atan2f(i1, r1);
        int base = (h * NPIX + n) * 32 + pair * 4;
        gp[base]     = m0; gp[base + 1] = p0;
        gp[base + 2] = m1; gp[base + 3] = p1;
    }
}

// ---------------- attention (f32x2, pipelined tiles) ----------------
// block: 512 threads = 128 q-rows x 4 key-splits; grid (18 q-tiles, 8 heads)
#define NQ 128
#define NSPLIT 4
#define TK 32
#define KPT (TK / NSPLIT)     // 8 keys per thread per tile
#define SSTRIDE 35            // u64 stride per score row (also reduction stride)
#define NTILE (NPIX / TK)     // 72

__global__ __launch_bounds__(512) void attn_kernel(
    float* __restrict__ qkm_o, float* __restrict__ qkp_o)
{
    __shared__ u64t  sbuf[NQ * SSTRIDE];      // packed (mag,phase) scores / reduction
    __shared__ float kvbuf[2 * TK * 32];      // K tile | V tile (interleaved pairs)

    float* kvK = kvbuf;
    float* kvV = kvbuf + TK * 32;

    const int h  = blockIdx.y;
    const int q0 = blockIdx.x * NQ;
    const int t  = threadIdx.x;
    const int s  = t >> 7;          // key split 0..3
    const int r  = t & 127;         // q row in tile
    const int qi = q0 + r;
    const float scale = 0.14433756729740643f;   // 1/sqrt(48)

    // q row as 16 packed (mag,phase) pairs, prescaled by `scale`
    u64t q[16];
    {
        const ulonglong2* qp = (const ulonglong2*)(g_q + ((size_t)(h * NPIX + qi)) * 32);
        u64t sc = pack2s(scale);
        #pragma unroll
        for (int d2 = 0; d2 < 8; d2++) {
            ulonglong2 v = qp[d2];
            q[2 * d2]     = fmul2(v.x, sc);
            q[2 * d2 + 1] = fmul2(v.y, sc);
        }
    }

    float mmax = -1e30f, lsum = 0.f;
    u64t acc[16];
    #pragma unroll
    for (int d = 0; d < 16; d++) acc[d] = 0ULL;

    // prefetch tile 0
    float4 pv;
    {
        const float* src = ((t < 256) ? g_k : g_v) + ((size_t)(h * NPIX)) * 32 + (size_t)(t & 255) * 4;
        pv = *(const float4*)src;
    }

    for (int it = 0; it < NTILE; it++) {
        __syncthreads();   // prev compute done (kv free), prev scores visible
        // store prefetched tile
        if (t < 256) ((float4*)kvK)[t] = pv;
        else         ((float4*)kvV)[t - 256] = pv;
        // prefetch next tile
        if (it < NTILE - 1) {
            const float* src = ((t < 256) ? g_k : g_v)
                + ((size_t)(h * NPIX + (it + 1) * TK)) * 32 + (size_t)(t & 255) * 4;
            pv = *(const float4*)src;
        }
        // writeout scores of previous tile (reads sbuf before it's overwritten)
        if (it > 0) {
            int ktp = (it - 1) * TK;
            for (int ii = t; ii < NQ * TK; ii += 512) {
                int row = ii >> 5, j = ii & 31;
                float lo, hi;
                unpack2(sbuf[row * SSTRIDE + j], lo, hi);
                size_t g = ((size_t)h * NPIX + q0 + row) * NPIX + ktp + j;
                qkm_o[g] = lo;
                qkp_o[g] = hi;
            }
        }
        __syncthreads();   // kv tile filled; writeout done

        // scores for my 8 keys (packed dot products)
        float a_abs[KPT];
        float tmax = -1e30f;
        #pragma unroll
        for (int jj = 0; jj < KPT; jj++) {
            int j = s * KPT + jj;
            const ulonglong2* krow = (const ulonglong2*)(kvK + j * 32);
            u64t dac = 0ULL;
            #pragma unroll
            for (int d2 = 0; d2 < 8; d2++) {
                ulonglong2 kk = krow[d2];
                dac = ffma2(q[2 * d2],     kk.x, dac);
                dac = ffma2(q[2 * d2 + 1], kk.y, dac);
            }
            sbuf[r * SSTRIDE + j] = dac;
            float smv, spv;
            unpack2(dac, smv, spv);
            a_abs[jj] = fabsf(smv);
            tmax = fmaxf(tmax, a_abs[jj]);
        }

        // tile-level online-softmax rescale
        float nm = fmaxf(mmax, tmax);
        float corr = __expf(mmax - nm);
        lsum *= corr;
        u64t cp = pack2s(corr);
        #pragma unroll
        for (int d = 0; d < 16; d++) acc[d] = fmul2(acc[d], cp);
        mmax = nm;

        #pragma unroll
        for (int jj = 0; jj < KPT; jj++) {
            int j = s * KPT + jj;
            float p = __expf(a_abs[jj] - nm);
            lsum += p;
            u64t pp = pack2s(p);
            const ulonglong2* vrow = (const ulonglong2*)(kvV + j * 32);
            #pragma unroll
            for (int d2 = 0; d2 < 8; d2++) {
                ulonglong2 vv = vrow[d2];
                acc[2 * d2]     = ffma2(pp, vv.x, acc[2 * d2]);
                acc[2 * d2 + 1] = ffma2(pp, vv.y, acc[2 * d2 + 1]);
            }
        }
    }

    // final tile's score writeout
    __syncthreads();
    {
        int ktp = (NTILE - 1) * TK;
        for (int ii = t; ii < NQ * TK; ii += 512) {
            int row = ii >> 5, j = ii & 31;
            float lo, hi;
            unpack2(sbuf[row * SSTRIDE + j], lo, hi);
            size_t g = ((size_t)h * NPIX + q0 + row) * NPIX + ktp + j;
            qkm_o[g] = lo;
            qkp_o[g] = hi;
        }
    }
    __syncthreads();

    // ---- reduce 4 splits per q row (2 pairwise rounds via sbuf) ----
    if (s >= 2) {
        u64t* dst = &sbuf[((s - 2) * NQ + r) * 17];
        dst[0] = pack2(mmax, lsum);
        #pragma unroll
        for (int d = 0; d < 16; d++) dst[1 + d] = acc[d];
    }
    __syncthreads();
    if (s < 2) {
        const u64t* src = &sbuf[(s * NQ + r) * 17];
        float m2, l2;
        unpack2(src[0], m2, l2);
        float M  = fmaxf(mmax, m2);
        float c0 = __expf(mmax - M), c1 = __expf(m2 - M);
        lsum = lsum * c0 + l2 * c1;
        u64t c0p = pack2s(c0), c1p = pack2s(c1);
        #pragma unroll
        for (int d = 0; d < 16; d++)
            acc[d] = fadd2(fmul2(acc[d], c0p), fmul2(src[1 + d], c1p));
        mmax = M;
    }
    __syncthreads();
    if (s == 1) {
        u64t* dst = &sbuf[r * 17];
        dst[0] = pack2(mmax, lsum);
        #pragma unroll
        for (int d = 0; d < 16; d++) dst[1 + d] = acc[d];
    }
    __syncthreads();
    if (s == 0) {
        const u64t* src = &sbuf[r * 17];
        float m2, l2;
        unpack2(src[0], m2, l2);
        float M  = fmaxf(mmax, m2);
        float c0 = __expf(mmax - M), c1 = __expf(m2 - M);
        float L  = lsum * c0 + l2 * c1;
        float invL = 1.f / L;
        u64t c0p = pack2s(c0), c1p = pack2s(c1);
        #pragma unroll
        for (int d = 0; d < 16; d++) {
            u64t cmb = fadd2(fmul2(acc[d], c0p), fmul2(src[1 + d], c1p));
            float amv, apv;
            unpack2(cmb, amv, apv);
            float omag = amv * invL;
            float oph  = apv * invL;
            float sn, cs;
            sincosf(oph, &sn, &cs);
            int c = h * HDIM + d;
            g_ar[c * NPIX + qi] = omag * cs;
            g_ai[c * NPIX + qi] = omag * sn;
        }
    }
}

// ---------------- launch ----------------
extern "C" void kernel_launch(void* const* d_in, const int* in_sizes, int n_in,
                              void* d_out, int out_size)
{
    (void)in_sizes; (void)n_in; (void)out_size;
    const float* xr = (const float*)d_in[0];
    const float* xi = (const float*)d_in[1];
    float* out = (float*)d_out;

    const size_t O_OR  = 0;
    const size_t O_OI  = (size_t)CHN * NPIX;                  // 294912
    const size_t O_QKM = O_OI + (size_t)CHN * NPIX;           // 589824
    const size_t O_QKP = O_QKM + (size_t)NHEAD * NPIX * NPIX;

    dim3 cb(24, 8);
    dim3 cg(CHN / CO_T, IMGH);

    // q, k, v complex convs with fused rotary/magphase epilogue
    cconv_kernel<<<cg, cb>>>(xr, xi, (const float*)d_in[2],  (const float*)d_in[3],
                             (const float*)d_in[4],  (const float*)d_in[5],
                             nullptr, nullptr, 0, 0);
    cconv_kernel<<<cg, cb>>>(xr, xi, (const float*)d_in[6],  (const float*)d_in[7],
                             (const float*)d_in[8],  (const float*)d_in[9],
                             nullptr, nullptr, 0, 1);
    cconv_kernel<<<cg, cb>>>(xr, xi, (const float*)d_in[10], (const float*)d_in[11],
                             (const float*)d_in[12], (const float*)d_in[13],
                             nullptr, nullptr, 0, 2);

    // attention (writes qkm/qkp directly, a_r/a_i to scratch)
    attn_kernel<<<dim3(NPIX / NQ, NHEAD), 512>>>(out + O_QKM, out + O_QKP);

    // output complex conv: reads g_ar/g_ai, writes o_r/o_i
    cconv_kernel<<<cg, cb>>>(nullptr, nullptr, (const float*)d_in[14], (const float*)d_in[15],
                             (const float*)d_in[16], (const float*)d_in[17],
                             out + O_OR, out + O_OI, 1, 3);
}